// round 2
// baseline (speedup 1.0000x reference)
#include <cuda_runtime.h>
#include <math.h>

// ---------------------------------------------------------------------------
// Problem constants
// ---------------------------------------------------------------------------
#define BATCH   8
#define RESO    64
#define LTOK    (RESO * RESO)        // 4096 tokens per image
#define CDIM    384
#define NHEAD   12
#define SPLITW  4
#define MLPH    (4 * CDIM)           // 1536
#define ROWS    (BATCH * LTOK)       // 32768
#define CB      (CDIM / 2)           // 192 per branch
#define NHB     (NHEAD / 2)          // 6 heads per branch
#define HD      32                   // head dim
#define NWIN    256                  // tokens per window (64*4)
#define WIN_PER_B 16
#define NWINDOWS (BATCH * WIN_PER_B) // 128 windows per branch

// ---------------------------------------------------------------------------
// Scratch (device globals; no allocation allowed)
// ---------------------------------------------------------------------------
__device__ float g_ln  [ROWS * CDIM];        // LN output (reused for LN1 & LN2)
__device__ float g_qkv [ROWS * 3 * CDIM];    // QKV
__device__ float g_attn[ROWS * CDIM];        // attention output (pre-proj)
__device__ float g_x1  [ROWS * CDIM];        // x + proj(attn)
__device__ float g_mlp [ROWS * MLPH];        // fc1/gelu output

// ---------------------------------------------------------------------------
// LayerNorm: one block per row (C=384), 128 threads, 3 elems/thread
// ---------------------------------------------------------------------------
__global__ __launch_bounds__(128) void ln_kernel(
    const float* __restrict__ x, const float* __restrict__ w,
    const float* __restrict__ b, float* __restrict__ out)
{
    int row = blockIdx.x;
    const float* xr = x + (size_t)row * CDIM;
    int t = threadIdx.x;

    float v0 = xr[t], v1 = xr[t + 128], v2 = xr[t + 256];
    float s  = v0 + v1 + v2;
    float ss = v0 * v0 + v1 * v1 + v2 * v2;

    #pragma unroll
    for (int o = 16; o > 0; o >>= 1) {
        s  += __shfl_down_sync(0xffffffffu, s,  o);
        ss += __shfl_down_sync(0xffffffffu, ss, o);
    }
    __shared__ float sh_s[4], sh_ss[4];
    __shared__ float sh_mu, sh_rstd;
    int wid = t >> 5, lane = t & 31;
    if (lane == 0) { sh_s[wid] = s; sh_ss[wid] = ss; }
    __syncthreads();
    if (t == 0) {
        float S  = sh_s[0] + sh_s[1] + sh_s[2] + sh_s[3];
        float SS = sh_ss[0] + sh_ss[1] + sh_ss[2] + sh_ss[3];
        float mu = S * (1.0f / CDIM);
        float var = SS * (1.0f / CDIM) - mu * mu;
        sh_mu = mu;
        sh_rstd = rsqrtf(var + 1e-5f);
    }
    __syncthreads();
    float mu = sh_mu, r = sh_rstd;
    float* orow = out + (size_t)row * CDIM;
    orow[t]       = (v0 - mu) * r * w[t]       + b[t];
    orow[t + 128] = (v1 - mu) * r * w[t + 128] + b[t + 128];
    orow[t + 256] = (v2 - mu) * r * w[t + 256] + b[t + 256];
}

// ---------------------------------------------------------------------------
// GEMM: Cout[M,N] = A[M,K] @ W[N,K]^T + bias (+ optional exact GELU, + residual)
// Tile 128x128x16, 256 threads, 8x8 micro-tile with strided (conflict-free)
// shared-memory reads.
// ---------------------------------------------------------------------------
__global__ __launch_bounds__(256) void gemm_kernel(
    const float* __restrict__ A, const float* __restrict__ Wt,
    const float* __restrict__ bias, const float* __restrict__ res,
    float* __restrict__ Cout, int M, int N, int K, int act_gelu)
{
    __shared__ float As[128][17];
    __shared__ float Ws[128][17];

    int n0 = blockIdx.x * 128;
    int m0 = blockIdx.y * 128;
    int t  = threadIdx.x;
    int ty = t >> 4;          // 0..15
    int tx = t & 15;          // 0..15

    float acc[8][8];
    #pragma unroll
    for (int i = 0; i < 8; i++)
        #pragma unroll
        for (int j = 0; j < 8; j++) acc[i][j] = 0.0f;

    for (int k0 = 0; k0 < K; k0 += 16) {
        // load A tile [128 x 16] and W tile [128 x 16]
        #pragma unroll
        for (int it = 0; it < 8; it++) {
            int e = t + it * 256;           // 0..2047
            int m = e >> 4, k = e & 15;
            As[m][k] = A[(size_t)(m0 + m) * K + k0 + k];
            Ws[m][k] = Wt[(size_t)(n0 + m) * K + k0 + k];
        }
        __syncthreads();

        #pragma unroll
        for (int kk = 0; kk < 16; kk++) {
            float a[8], bb[8];
            #pragma unroll
            for (int i = 0; i < 8; i++) a[i]  = As[ty + i * 16][kk];
            #pragma unroll
            for (int j = 0; j < 8; j++) bb[j] = Ws[tx + j * 16][kk];
            #pragma unroll
            for (int i = 0; i < 8; i++)
                #pragma unroll
                for (int j = 0; j < 8; j++)
                    acc[i][j] += a[i] * bb[j];
        }
        __syncthreads();
    }

    #pragma unroll
    for (int i = 0; i < 8; i++) {
        int m = m0 + ty + i * 16;
        #pragma unroll
        for (int j = 0; j < 8; j++) {
            int n = n0 + tx + j * 16;
            float c = acc[i][j] + bias[n];
            if (act_gelu) c = 0.5f * c * (1.0f + erff(c * 0.70710678118654752f));
            if (res) c += res[(size_t)m * N + n];
            Cout[(size_t)m * N + n] = c;
        }
    }
}

// ---------------------------------------------------------------------------
// Windowed attention + LePE, one block per (window, head).
//   branch 0: windows 64x4 (H_sp=64, W_sp=4)
//   branch 1: windows 4x64 (H_sp=4,  W_sp=64)
// N=256 tokens/window, hd=32. One thread per query token; Q,K,V staged in
// dynamic smem; online softmax in registers; LePE 3x3 depthwise conv computed
// from the V tile in smem and fused into the output write.
// ---------------------------------------------------------------------------
__global__ __launch_bounds__(256) void attn_kernel(
    const float* __restrict__ qkv,
    const float* __restrict__ lw0, const float* __restrict__ lb0,
    const float* __restrict__ lw1, const float* __restrict__ lb1,
    float* __restrict__ out)
{
    extern __shared__ float smem[];
    float* Qs = smem;             // [256][32]
    float* Ks = smem + 8192;      // [256][32]
    float* Vs = smem + 16384;     // [256][32]
    __shared__ float wsh[32 * 9];
    __shared__ float bsh[32];

    int branch = blockIdx.y;
    int wh  = blockIdx.x;
    int win = wh / NHB;
    int hh  = wh % NHB;
    int batch = win / WIN_PER_B;
    int wloc  = win % WIN_PER_B;
    int t = threadIdx.x;

    const float* wptr = branch ? lw1 : lw0;
    const float* bptr = branch ? lb1 : lb0;
    // FIX (R1 bug): 288 > blockDim; must grid-stride, else wsh[256..287]
    // held garbage (LePE weights for channels d>=28 of every head).
    for (int e = t; e < 288; e += 256) wsh[e] = wptr[hh * 288 + e];
    if (t < 32) bsh[t] = bptr[hh * 32 + t];

    int cbase = branch * CB + hh * HD;

    // stage Q, K, V for the window
    #pragma unroll 4
    for (int e = t; e < NWIN * HD; e += 256) {
        int n = e >> 5, d = e & 31;
        int l;
        if (branch == 0) l = (n >> 2) * 64 + wloc * 4 + (n & 3);
        else             l = (wloc * 4 + (n >> 6)) * 64 + (n & 63);
        size_t rowoff = ((size_t)batch * LTOK + l) * (3 * CDIM) + cbase + d;
        Qs[e] = qkv[rowoff];
        Ks[e] = qkv[rowoff + CDIM];
        Vs[e] = qkv[rowoff + 2 * CDIM];
    }
    __syncthreads();

    // one query per thread
    const float scale = 0.17677669529663687f;   // 1/sqrt(32)
    int n = t;
    float q[HD];
    #pragma unroll
    for (int d = 0; d < HD; d++) q[d] = Qs[n * HD + d] * scale;

    float m = -1e30f, lsum = 0.0f;
    float acc[HD];
    #pragma unroll
    for (int d = 0; d < HD; d++) acc[d] = 0.0f;

    for (int j = 0; j < NWIN; j++) {
        const float* kj = Ks + j * HD;
        float s = 0.0f;
        #pragma unroll
        for (int d = 0; d < HD; d++) s += q[d] * kj[d];
        const float* vj = Vs + j * HD;
        if (s <= m) {
            float p = __expf(s - m);
            lsum += p;
            #pragma unroll
            for (int d = 0; d < HD; d++) acc[d] += p * vj[d];
        } else {
            float f = __expf(m - s);
            lsum = lsum * f + 1.0f;
            #pragma unroll
            for (int d = 0; d < HD; d++) acc[d] = acc[d] * f + vj[d];
            m = s;
        }
    }
    float inv = 1.0f / lsum;

    // LePE: 3x3 depthwise conv on the window image of V (zero padding at
    // window borders), cross-correlation orientation (matches XLA conv).
    int Hh = branch ? 4 : 64;
    int Wd = branch ? 64 : 4;
    int r  = n / Wd;
    int cc = n % Wd;
    int l;
    if (branch == 0) l = (n >> 2) * 64 + wloc * 4 + (n & 3);
    else             l = (wloc * 4 + (n >> 6)) * 64 + (n & 63);
    float* orow = out + ((size_t)batch * LTOK + l) * CDIM + cbase;

    #pragma unroll
    for (int d = 0; d < HD; d++) {
        float lep = bsh[d];
        #pragma unroll
        for (int dr = -1; dr <= 1; dr++) {
            int rr = r + dr;
            if (rr < 0 || rr >= Hh) continue;
            #pragma unroll
            for (int dc = -1; dc <= 1; dc++) {
                int c2 = cc + dc;
                if (c2 < 0 || c2 >= Wd) continue;
                lep += Vs[(rr * Wd + c2) * HD + d] * wsh[d * 9 + (dr + 1) * 3 + (dc + 1)];
            }
        }
        orow[d] = acc[d] * inv + lep;
    }
}

// ---------------------------------------------------------------------------
// Launch
// ---------------------------------------------------------------------------
extern "C" void kernel_launch(void* const* d_in, const int* in_sizes, int n_in,
                              void* d_out, int out_size)
{
    const float* x      = (const float*)d_in[0];
    const float* ln1_w  = (const float*)d_in[1];
    const float* ln1_b  = (const float*)d_in[2];
    const float* qkv_w  = (const float*)d_in[3];
    const float* qkv_b  = (const float*)d_in[4];
    const float* lw0    = (const float*)d_in[5];
    const float* lb0    = (const float*)d_in[6];
    const float* lw1    = (const float*)d_in[7];
    const float* lb1    = (const float*)d_in[8];
    const float* proj_w = (const float*)d_in[9];
    const float* proj_b = (const float*)d_in[10];
    const float* ln2_w  = (const float*)d_in[11];
    const float* ln2_b  = (const float*)d_in[12];
    const float* fc1_w  = (const float*)d_in[13];
    const float* fc1_b  = (const float*)d_in[14];
    const float* fc2_w  = (const float*)d_in[15];
    const float* fc2_b  = (const float*)d_in[16];
    float* out = (float*)d_out;

    float *p_ln, *p_qkv, *p_attn, *p_x1, *p_mlp;
    cudaGetSymbolAddress((void**)&p_ln,   g_ln);
    cudaGetSymbolAddress((void**)&p_qkv,  g_qkv);
    cudaGetSymbolAddress((void**)&p_attn, g_attn);
    cudaGetSymbolAddress((void**)&p_x1,   g_x1);
    cudaGetSymbolAddress((void**)&p_mlp,  g_mlp);

    cudaFuncSetAttribute(attn_kernel,
                         cudaFuncAttributeMaxDynamicSharedMemorySize, 98304);

    // 1) LN1
    ln_kernel<<<ROWS, 128>>>(x, ln1_w, ln1_b, p_ln);

    // 2) QKV GEMM: [32768,384] @ [1152,384]^T
    gemm_kernel<<<dim3(3 * CDIM / 128, ROWS / 128), 256>>>(
        p_ln, qkv_w, qkv_b, nullptr, p_qkv, ROWS, 3 * CDIM, CDIM, 0);

    // 3) windowed attention + LePE (both branches)
    attn_kernel<<<dim3(NWINDOWS * NHB, 2), 256, 98304>>>(
        p_qkv, lw0, lb0, lw1, lb1, p_attn);

    // 4) proj GEMM + residual(x)
    gemm_kernel<<<dim3(CDIM / 128, ROWS / 128), 256>>>(
        p_attn, proj_w, proj_b, x, p_x1, ROWS, CDIM, CDIM, 0);

    // 5) LN2
    ln_kernel<<<ROWS, 128>>>(p_x1, ln2_w, ln2_b, p_ln);

    // 6) fc1 GEMM + exact GELU
    gemm_kernel<<<dim3(MLPH / 128, ROWS / 128), 256>>>(
        p_ln, fc1_w, fc1_b, nullptr, p_mlp, ROWS, MLPH, CDIM, 1);

    // 7) fc2 GEMM + residual(x1) -> out
    gemm_kernel<<<dim3(CDIM / 128, ROWS / 128), 256>>>(
        p_mlp, fc2_w, fc2_b, p_x1, out, ROWS, CDIM, MLPH, 0);
}

// round 3
// speedup vs baseline: 2.1683x; 2.1683x over previous
#include <cuda_runtime.h>
#include <math.h>
#include <stdint.h>

// ---------------------------------------------------------------------------
// Problem constants
// ---------------------------------------------------------------------------
#define BATCH   8
#define RESO    64
#define LTOK    (RESO * RESO)        // 4096 tokens per image
#define CDIM    384
#define NHEAD   12
#define MLPH    (4 * CDIM)           // 1536
#define ROWS    (BATCH * LTOK)       // 32768
#define CB      (CDIM / 2)           // 192 per branch
#define NHB     (NHEAD / 2)          // 6 heads per branch
#define HD      32                   // head dim
#define NWIN    256                  // tokens per window
#define WIN_PER_B 16
#define NWINDOWS (BATCH * WIN_PER_B) // 128 windows per branch

// ---------------------------------------------------------------------------
// Scratch (device globals; no allocation allowed)
// ---------------------------------------------------------------------------
__device__ float g_ln  [ROWS * CDIM];
__device__ float g_qkv [ROWS * 3 * CDIM];
__device__ float g_attn[ROWS * CDIM];
__device__ float g_x1  [ROWS * CDIM];
__device__ float g_mlp [ROWS * MLPH];
// tf32-rounded weight copies
__device__ float g_wq [3 * CDIM * CDIM];
__device__ float g_wp [CDIM * CDIM];
__device__ float g_w1 [MLPH * CDIM];
__device__ float g_w2 [CDIM * MLPH];

__device__ __forceinline__ float to_tf32(float x) {
    unsigned u;
    asm("cvt.rna.tf32.f32 %0, %1;" : "=r"(u) : "f"(x));
    return __uint_as_float(u);
}

// ---------------------------------------------------------------------------
// Round fp32 array to tf32 (for weights)
// ---------------------------------------------------------------------------
__global__ void round_tf32_kernel(const float* __restrict__ in,
                                  float* __restrict__ outp, int n)
{
    int i = blockIdx.x * 256 + threadIdx.x;
    if (i < n) outp[i] = to_tf32(in[i]);
}

// ---------------------------------------------------------------------------
// LayerNorm (output rounded to tf32 — always feeds a GEMM A operand)
// ---------------------------------------------------------------------------
__global__ __launch_bounds__(128) void ln_kernel(
    const float* __restrict__ x, const float* __restrict__ w,
    const float* __restrict__ b, float* __restrict__ out)
{
    int row = blockIdx.x;
    const float* xr = x + (size_t)row * CDIM;
    int t = threadIdx.x;

    float v0 = xr[t], v1 = xr[t + 128], v2 = xr[t + 256];
    float s  = v0 + v1 + v2;
    float ss = v0 * v0 + v1 * v1 + v2 * v2;

    #pragma unroll
    for (int o = 16; o > 0; o >>= 1) {
        s  += __shfl_down_sync(0xffffffffu, s,  o);
        ss += __shfl_down_sync(0xffffffffu, ss, o);
    }
    __shared__ float sh_s[4], sh_ss[4];
    __shared__ float sh_mu, sh_rstd;
    int wid = t >> 5, lane = t & 31;
    if (lane == 0) { sh_s[wid] = s; sh_ss[wid] = ss; }
    __syncthreads();
    if (t == 0) {
        float S  = sh_s[0] + sh_s[1] + sh_s[2] + sh_s[3];
        float SS = sh_ss[0] + sh_ss[1] + sh_ss[2] + sh_ss[3];
        float mu = S * (1.0f / CDIM);
        float var = SS * (1.0f / CDIM) - mu * mu;
        sh_mu = mu;
        sh_rstd = rsqrtf(var + 1e-5f);
    }
    __syncthreads();
    float mu = sh_mu, r = sh_rstd;
    float* orow = out + (size_t)row * CDIM;
    orow[t]       = to_tf32((v0 - mu) * r * w[t]       + b[t]);
    orow[t + 128] = to_tf32((v1 - mu) * r * w[t + 128] + b[t + 128]);
    orow[t + 256] = to_tf32((v2 - mu) * r * w[t + 256] + b[t + 256]);
}

// ---------------------------------------------------------------------------
// TF32 tensor-core GEMM: C[M,N] = A[M,K] @ W[N,K]^T + bias
//   optional exact GELU, optional residual add, optional tf32-round of output.
// Block tile 128x128x32, 256 threads (8 warps, 4x2), warp tile 32x64,
// cp.async double-buffered smem, mma.sync m16n8k8 tf32.
// A and W must already be tf32-rounded values stored as fp32.
// ---------------------------------------------------------------------------
#define PADK 36   // 32 + 4 pad: conflict-free fragment loads

__device__ __forceinline__ void cp16(uint32_t dst, const float* src) {
    asm volatile("cp.async.ca.shared.global [%0], [%1], 16;\n"
                 :: "r"(dst), "l"(src));
}

__global__ __launch_bounds__(256, 2) void gemm_tc_kernel(
    const float* __restrict__ A, const float* __restrict__ Wt,
    const float* __restrict__ bias, const float* __restrict__ res,
    float* __restrict__ Cout, int M, int N, int K,
    int act_gelu, int round_out)
{
    extern __shared__ float smem[];
    float* As[2] = { smem,                smem + 2 * 128 * PADK };
    float* Bs[2] = { smem + 128 * PADK,   smem + 3 * 128 * PADK };

    int n0 = blockIdx.x * 128;
    int m0 = blockIdx.y * 128;
    int t  = threadIdx.x;
    int w  = t >> 5;
    int lane = t & 31;
    int g   = lane >> 2;      // group id 0..7
    int tig = lane & 3;       // thread-in-group 0..3
    int wm  = w >> 1;         // 0..3  (M direction)
    int wn  = w & 1;          // 0..1  (N direction)

    float acc[2][8][4];
    #pragma unroll
    for (int i = 0; i < 2; i++)
        #pragma unroll
        for (int j = 0; j < 8; j++)
            #pragma unroll
            for (int r = 0; r < 4; r++) acc[i][j][r] = 0.0f;

    // staging: 4 chunks of 16B each for A and for B per thread
    uint32_t sA[2], sB[2];
    {
        uint32_t base = (uint32_t)__cvta_generic_to_shared(smem);
        sA[0] = base;
        sB[0] = base + 128 * PADK * 4;
        sA[1] = base + 2 * 128 * PADK * 4;
        sB[1] = base + 3 * 128 * PADK * 4;
    }

    int nstage = K / 32;

    // prologue: stage 0
    {
        #pragma unroll
        for (int i = 0; i < 4; i++) {
            int e = t + i * 256;
            int row = e >> 3, c4 = (e & 7) * 4;
            cp16(sA[0] + (row * PADK + c4) * 4, A  + (size_t)(m0 + row) * K + c4);
            cp16(sB[0] + (row * PADK + c4) * 4, Wt + (size_t)(n0 + row) * K + c4);
        }
        asm volatile("cp.async.commit_group;\n");
    }

    for (int it = 0; it < nstage; it++) {
        asm volatile("cp.async.wait_group 0;\n");
        __syncthreads();
        int cur = it & 1;
        if (it + 1 < nstage) {
            int nxt = cur ^ 1;
            int k0 = (it + 1) * 32;
            #pragma unroll
            for (int i = 0; i < 4; i++) {
                int e = t + i * 256;
                int row = e >> 3, c4 = (e & 7) * 4;
                cp16(sA[nxt] + (row * PADK + c4) * 4,
                     A  + (size_t)(m0 + row) * K + k0 + c4);
                cp16(sB[nxt] + (row * PADK + c4) * 4,
                     Wt + (size_t)(n0 + row) * K + k0 + c4);
            }
            asm volatile("cp.async.commit_group;\n");
        }

        const float* Asc = As[cur];
        const float* Bsc = Bs[cur];
        #pragma unroll
        for (int kk = 0; kk < 32; kk += 8) {
            uint32_t a[2][4];
            #pragma unroll
            for (int mi = 0; mi < 2; mi++) {
                int r0 = wm * 32 + mi * 16 + g;
                a[mi][0] = __float_as_uint(Asc[(r0    ) * PADK + kk + tig    ]);
                a[mi][1] = __float_as_uint(Asc[(r0 + 8) * PADK + kk + tig    ]);
                a[mi][2] = __float_as_uint(Asc[(r0    ) * PADK + kk + tig + 4]);
                a[mi][3] = __float_as_uint(Asc[(r0 + 8) * PADK + kk + tig + 4]);
            }
            uint32_t b[8][2];
            #pragma unroll
            for (int nj = 0; nj < 8; nj++) {
                int c0 = wn * 64 + nj * 8 + g;
                b[nj][0] = __float_as_uint(Bsc[c0 * PADK + kk + tig    ]);
                b[nj][1] = __float_as_uint(Bsc[c0 * PADK + kk + tig + 4]);
            }
            #pragma unroll
            for (int mi = 0; mi < 2; mi++)
                #pragma unroll
                for (int nj = 0; nj < 8; nj++) {
                    asm volatile(
                        "mma.sync.aligned.m16n8k8.row.col.f32.tf32.tf32.f32 "
                        "{%0,%1,%2,%3}, {%4,%5,%6,%7}, {%8,%9}, {%0,%1,%2,%3};\n"
                        : "+f"(acc[mi][nj][0]), "+f"(acc[mi][nj][1]),
                          "+f"(acc[mi][nj][2]), "+f"(acc[mi][nj][3])
                        : "r"(a[mi][0]), "r"(a[mi][1]), "r"(a[mi][2]), "r"(a[mi][3]),
                          "r"(b[nj][0]), "r"(b[nj][1]));
                }
        }
        __syncthreads();
    }

    // epilogue
    #pragma unroll
    for (int mi = 0; mi < 2; mi++) {
        int r0 = m0 + wm * 32 + mi * 16 + g;
        #pragma unroll
        for (int nj = 0; nj < 8; nj++) {
            int c = n0 + wn * 64 + nj * 8 + tig * 2;
            float b0 = bias[c], b1 = bias[c + 1];
            #pragma unroll
            for (int half = 0; half < 2; half++) {
                int rr = r0 + half * 8;
                float v0 = acc[mi][nj][half * 2 + 0] + b0;
                float v1 = acc[mi][nj][half * 2 + 1] + b1;
                if (act_gelu) {
                    v0 = 0.5f * v0 * (1.0f + erff(v0 * 0.70710678118654752f));
                    v1 = 0.5f * v1 * (1.0f + erff(v1 * 0.70710678118654752f));
                }
                if (res) {
                    v0 += res[(size_t)rr * N + c];
                    v1 += res[(size_t)rr * N + c + 1];
                }
                if (round_out) { v0 = to_tf32(v0); v1 = to_tf32(v1); }
                float2 vv = make_float2(v0, v1);
                *(float2*)(Cout + (size_t)rr * N + c) = vv;
            }
        }
    }
}

// ---------------------------------------------------------------------------
// Windowed attention + LePE (unchanged from R2 except tf32-rounded output,
// since g_attn is the A operand of the proj GEMM).
// ---------------------------------------------------------------------------
__global__ __launch_bounds__(256) void attn_kernel(
    const float* __restrict__ qkv,
    const float* __restrict__ lw0, const float* __restrict__ lb0,
    const float* __restrict__ lw1, const float* __restrict__ lb1,
    float* __restrict__ out)
{
    extern __shared__ float smem[];
    float* Qs = smem;             // [256][32]
    float* Ks = smem + 8192;      // [256][32]
    float* Vs = smem + 16384;     // [256][32]
    __shared__ float wsh[32 * 9];
    __shared__ float bsh[32];

    int branch = blockIdx.y;
    int wh  = blockIdx.x;
    int win = wh / NHB;
    int hh  = wh % NHB;
    int batch = win / WIN_PER_B;
    int wloc  = win % WIN_PER_B;
    int t = threadIdx.x;

    const float* wptr = branch ? lw1 : lw0;
    const float* bptr = branch ? lb1 : lb0;
    for (int e = t; e < 288; e += 256) wsh[e] = wptr[hh * 288 + e];
    if (t < 32) bsh[t] = bptr[hh * 32 + t];

    int cbase = branch * CB + hh * HD;

    #pragma unroll 4
    for (int e = t; e < NWIN * HD; e += 256) {
        int n = e >> 5, d = e & 31;
        int l;
        if (branch == 0) l = (n >> 2) * 64 + wloc * 4 + (n & 3);
        else             l = (wloc * 4 + (n >> 6)) * 64 + (n & 63);
        size_t rowoff = ((size_t)batch * LTOK + l) * (3 * CDIM) + cbase + d;
        Qs[e] = qkv[rowoff];
        Ks[e] = qkv[rowoff + CDIM];
        Vs[e] = qkv[rowoff + 2 * CDIM];
    }
    __syncthreads();

    const float scale = 0.17677669529663687f;   // 1/sqrt(32)
    int n = t;
    float q[HD];
    #pragma unroll
    for (int d = 0; d < HD; d++) q[d] = Qs[n * HD + d] * scale;

    float m = -1e30f, lsum = 0.0f;
    float acc[HD];
    #pragma unroll
    for (int d = 0; d < HD; d++) acc[d] = 0.0f;

    for (int j = 0; j < NWIN; j++) {
        const float* kj = Ks + j * HD;
        float s = 0.0f;
        #pragma unroll
        for (int d = 0; d < HD; d++) s += q[d] * kj[d];
        const float* vj = Vs + j * HD;
        if (s <= m) {
            float p = __expf(s - m);
            lsum += p;
            #pragma unroll
            for (int d = 0; d < HD; d++) acc[d] += p * vj[d];
        } else {
            float f = __expf(m - s);
            lsum = lsum * f + 1.0f;
            #pragma unroll
            for (int d = 0; d < HD; d++) acc[d] = acc[d] * f + vj[d];
            m = s;
        }
    }
    float inv = 1.0f / lsum;

    int Hh = branch ? 4 : 64;
    int Wd = branch ? 64 : 4;
    int r  = n / Wd;
    int cc = n % Wd;
    int l;
    if (branch == 0) l = (n >> 2) * 64 + wloc * 4 + (n & 3);
    else             l = (wloc * 4 + (n >> 6)) * 64 + (n & 63);
    float* orow = out + ((size_t)batch * LTOK + l) * CDIM + cbase;

    #pragma unroll
    for (int d = 0; d < HD; d++) {
        float lep = bsh[d];
        #pragma unroll
        for (int dr = -1; dr <= 1; dr++) {
            int rr = r + dr;
            if (rr < 0 || rr >= Hh) continue;
            #pragma unroll
            for (int dc = -1; dc <= 1; dc++) {
                int c2 = cc + dc;
                if (c2 < 0 || c2 >= Wd) continue;
                lep += Vs[(rr * Wd + c2) * HD + d] * wsh[d * 9 + (dr + 1) * 3 + (dc + 1)];
            }
        }
        orow[d] = to_tf32(acc[d] * inv + lep);
    }
}

// ---------------------------------------------------------------------------
// Launch
// ---------------------------------------------------------------------------
#define GEMM_SMEM (4 * 128 * PADK * 4)   // 73728 bytes

extern "C" void kernel_launch(void* const* d_in, const int* in_sizes, int n_in,
                              void* d_out, int out_size)
{
    const float* x      = (const float*)d_in[0];
    const float* ln1_w  = (const float*)d_in[1];
    const float* ln1_b  = (const float*)d_in[2];
    const float* qkv_w  = (const float*)d_in[3];
    const float* qkv_b  = (const float*)d_in[4];
    const float* lw0    = (const float*)d_in[5];
    const float* lb0    = (const float*)d_in[6];
    const float* lw1    = (const float*)d_in[7];
    const float* lb1    = (const float*)d_in[8];
    const float* proj_w = (const float*)d_in[9];
    const float* proj_b = (const float*)d_in[10];
    const float* ln2_w  = (const float*)d_in[11];
    const float* ln2_b  = (const float*)d_in[12];
    const float* fc1_w  = (const float*)d_in[13];
    const float* fc1_b  = (const float*)d_in[14];
    const float* fc2_w  = (const float*)d_in[15];
    const float* fc2_b  = (const float*)d_in[16];
    float* out = (float*)d_out;

    float *p_ln, *p_qkv, *p_attn, *p_x1, *p_mlp, *p_wq, *p_wp, *p_w1, *p_w2;
    cudaGetSymbolAddress((void**)&p_ln,   g_ln);
    cudaGetSymbolAddress((void**)&p_qkv,  g_qkv);
    cudaGetSymbolAddress((void**)&p_attn, g_attn);
    cudaGetSymbolAddress((void**)&p_x1,   g_x1);
    cudaGetSymbolAddress((void**)&p_mlp,  g_mlp);
    cudaGetSymbolAddress((void**)&p_wq,   g_wq);
    cudaGetSymbolAddress((void**)&p_wp,   g_wp);
    cudaGetSymbolAddress((void**)&p_w1,   g_w1);
    cudaGetSymbolAddress((void**)&p_w2,   g_w2);

    cudaFuncSetAttribute(attn_kernel,
                         cudaFuncAttributeMaxDynamicSharedMemorySize, 98304);
    cudaFuncSetAttribute(gemm_tc_kernel,
                         cudaFuncAttributeMaxDynamicSharedMemorySize, GEMM_SMEM);

    // 0) round weights to tf32
    round_tf32_kernel<<<(3*CDIM*CDIM + 255)/256, 256>>>(qkv_w,  p_wq, 3*CDIM*CDIM);
    round_tf32_kernel<<<(CDIM*CDIM   + 255)/256, 256>>>(proj_w, p_wp, CDIM*CDIM);
    round_tf32_kernel<<<(MLPH*CDIM   + 255)/256, 256>>>(fc1_w,  p_w1, MLPH*CDIM);
    round_tf32_kernel<<<(CDIM*MLPH   + 255)/256, 256>>>(fc2_w,  p_w2, CDIM*MLPH);

    // 1) LN1 (tf32-rounded output)
    ln_kernel<<<ROWS, 128>>>(x, ln1_w, ln1_b, p_ln);

    // 2) QKV GEMM
    gemm_tc_kernel<<<dim3(3*CDIM/128, ROWS/128), 256, GEMM_SMEM>>>(
        p_ln, p_wq, qkv_b, nullptr, p_qkv, ROWS, 3*CDIM, CDIM, 0, 0);

    // 3) windowed attention + LePE (tf32-rounded output)
    attn_kernel<<<dim3(NWINDOWS * NHB, 2), 256, 98304>>>(
        p_qkv, lw0, lb0, lw1, lb1, p_attn);

    // 4) proj GEMM + residual(x)  (exact output)
    gemm_tc_kernel<<<dim3(CDIM/128, ROWS/128), 256, GEMM_SMEM>>>(
        p_attn, p_wp, proj_b, x, p_x1, ROWS, CDIM, CDIM, 0, 0);

    // 5) LN2 (tf32-rounded output)
    ln_kernel<<<ROWS, 128>>>(p_x1, ln2_w, ln2_b, p_ln);

    // 6) fc1 GEMM + exact GELU (tf32-rounded output)
    gemm_tc_kernel<<<dim3(MLPH/128, ROWS/128), 256, GEMM_SMEM>>>(
        p_ln, p_w1, fc1_b, nullptr, p_mlp, ROWS, MLPH, CDIM, 1, 1);

    // 7) fc2 GEMM + residual(x1) -> out (exact)
    gemm_tc_kernel<<<dim3(CDIM/128, ROWS/128), 256, GEMM_SMEM>>>(
        p_mlp, p_w2, fc2_b, p_x1, out, ROWS, CDIM, MLPH, 0, 0);
}